// round 7
// baseline (speedup 1.0000x reference)
#include <cuda_runtime.h>
#include <cuda_bf16.h>
#include <math.h>

#define TT   2048
#define HH   16
#define DQK  192
#define NOPE 128
#define ROPE 64
#define LORA 512
#define VD   128
#define SCALE_F (0.07216878364870322f)  // 1/sqrt(192)

// Scratch (allowed: __device__ globals, no runtime allocation)
__device__ float g_K[HH * TT * DQK];   // per-head K = [k_nope | k_pe]
__device__ float g_V[HH * TT * VD];    // per-head effective V = k_c @ w_uv[h]

// ---------------------------------------------------------------------------
// Projection kernel:
//   z==0: g_K[h][t][0:128] = k_c[t] @ w_kv_b[:, h*256 : h*256+128]
//         g_K[h][t][128:192] = k_pe[t]
//   z==1: g_V[h][t][:] = k_c[t] @ w_uv[h]
// Block: 256 threads, computes a 64x128 output tile. Grid: (T/64, H, 2).
// ---------------------------------------------------------------------------
__global__ __launch_bounds__(256)
void proj_kernel(const float* __restrict__ kc, const float* __restrict__ wkv,
                 const float* __restrict__ wuv, const float* __restrict__ kpe)
{
    const int rbase = blockIdx.x * 64;
    const int h     = blockIdx.y;
    const int which = blockIdx.z;

    __shared__ float a_s[32 * 68];    // A chunk, transposed: a_s[l][row]
    __shared__ float b_s[32 * 132];   // B chunk: b_s[l][n]

    const int tid = threadIdx.x;
    const int ty  = tid >> 4;         // 0..15
    const int tx  = tid & 15;         // 0..15

    float acc[4][8];
    #pragma unroll
    for (int i = 0; i < 4; i++)
        #pragma unroll
        for (int j = 0; j < 8; j++) acc[i][j] = 0.0f;

    const float* Bp      = (which == 0) ? (wkv + h * 256) : (wuv + (size_t)h * LORA * VD);
    const int    bstride = (which == 0) ? (HH * 256) : VD;

    for (int lc = 0; lc < LORA; lc += 32) {
        // Load A (64 rows x 32 l), store transposed
        #pragma unroll
        for (int i = tid; i < 64 * 32; i += 256) {
            int row = i >> 5, l = i & 31;
            a_s[l * 68 + row] = kc[(rbase + row) * LORA + lc + l];
        }
        // Load B (32 l x 128 n)
        #pragma unroll
        for (int i = tid; i < 32 * 128; i += 256) {
            int l = i >> 7, n = i & 127;
            b_s[l * 132 + n] = Bp[(size_t)(lc + l) * bstride + n];
        }
        __syncthreads();

        #pragma unroll
        for (int kk = 0; kk < 32; kk++) {
            float4 a4 = *(const float4*)&a_s[kk * 68 + ty * 4];
            float4 b0 = *(const float4*)&b_s[kk * 132 + tx * 8];
            float4 b1 = *(const float4*)&b_s[kk * 132 + tx * 8 + 4];
            float av[4] = {a4.x, a4.y, a4.z, a4.w};
            float bv[8] = {b0.x, b0.y, b0.z, b0.w, b1.x, b1.y, b1.z, b1.w};
            #pragma unroll
            for (int ii = 0; ii < 4; ii++)
                #pragma unroll
                for (int jj = 0; jj < 8; jj++)
                    acc[ii][jj] += av[ii] * bv[jj];
        }
        __syncthreads();
    }

    if (which == 0) {
        #pragma unroll
        for (int ii = 0; ii < 4; ii++) {
            int t = rbase + ty * 4 + ii;
            float* dst = &g_K[((size_t)h * TT + t) * DQK + tx * 8];
            #pragma unroll
            for (int jj = 0; jj < 8; jj++) dst[jj] = acc[ii][jj];
        }
        // RoPE tail: broadcast k_pe into dims [128:192]
        #pragma unroll
        for (int i = tid; i < 64 * 64; i += 256) {
            int row = i >> 6, dd = i & 63;
            g_K[((size_t)h * TT + rbase + row) * DQK + NOPE + dd] =
                kpe[(rbase + row) * ROPE + dd];
        }
    } else {
        #pragma unroll
        for (int ii = 0; ii < 4; ii++) {
            int t = rbase + ty * 4 + ii;
            float* dst = &g_V[((size_t)h * TT + t) * VD + tx * 8];
            #pragma unroll
            for (int jj = 0; jj < 8; jj++) dst[jj] = acc[ii][jj];
        }
    }
}

// ---------------------------------------------------------------------------
// Causal flash attention, one head x 64-query tile per block, 256 threads.
// d_qk = 192, d_v = 128. fp32 throughout. Online softmax.
// smem: Q[64][196] | Ktr[64][68] (one 64-d chunk, transposed) | V[64][132]
//       | S[64][65] | m/l/scale[64]
// ---------------------------------------------------------------------------
#define ATTN_SMEM_FLOATS (64 * 196 + 64 * 68 + 64 * 132 + 64 * 65 + 3 * 64)

__global__ __launch_bounds__(256)
void attn_kernel(const float* __restrict__ q, float* __restrict__ out)
{
    extern __shared__ float sm[];
    float* q_s  = sm;                       // 64*196 = 12544
    float* k_s  = q_s + 64 * 196;           // 64*68  =  4352  (k_s[d][s])
    float* v_s  = k_s + 64 * 68;            // 64*132 =  8448
    float* S    = v_s + 64 * 132;           // 64*65  =  4160
    float* m_s  = S + 64 * 65;              // 64
    float* l_s  = m_s + 64;                 // 64
    float* sc_s = l_s + 64;                 // 64

    const int h     = blockIdx.y;
    const int qbase = blockIdx.x * 64;
    const int tid   = threadIdx.x;
    const int ty    = tid >> 4;
    const int tx    = tid & 15;

    // Load Q tile (64 x 192)
    for (int i = tid; i < 64 * 192; i += 256) {
        int r = i / 192, d = i - r * 192;
        q_s[r * 196 + d] = q[((size_t)(qbase + r) * HH + h) * DQK + d];
    }
    if (tid < 64) { m_s[tid] = -3.0e38f; l_s[tid] = 0.0f; }

    float o[4][8];
    #pragma unroll
    for (int i = 0; i < 4; i++)
        #pragma unroll
        for (int j = 0; j < 8; j++) o[i][j] = 0.0f;

    __syncthreads();

    const float* Kg = g_K + (size_t)h * TT * DQK;
    const float* Vg = g_V + (size_t)h * TT * VD;
    const int ntiles = blockIdx.x + 1;

    for (int tile = 0; tile < ntiles; tile++) {
        const int sbase = tile * 64;

        // --- Phase A: S = Q K^T (accumulate over 3 chunks of 64 dims) ---
        float sa[4][4];
        #pragma unroll
        for (int i = 0; i < 4; i++)
            #pragma unroll
            for (int j = 0; j < 4; j++) sa[i][j] = 0.0f;

        for (int c = 0; c < 3; c++) {
            // Load K chunk transposed: k_s[d][s]
            #pragma unroll
            for (int i = tid; i < 64 * 64; i += 256) {
                int s = i >> 6, d = i & 63;
                k_s[d * 68 + s] = Kg[(size_t)(sbase + s) * DQK + c * 64 + d];
            }
            __syncthreads();

            const float* qp = q_s + (ty * 4) * 196 + c * 64;
            const float* kp = k_s + tx * 4;
            #pragma unroll 8
            for (int d = 0; d < 64; d++) {
                float4 k4 = *(const float4*)(kp + d * 68);
                float q0 = qp[d];
                float q1 = qp[196 + d];
                float q2 = qp[392 + d];
                float q3 = qp[588 + d];
                sa[0][0] += q0 * k4.x; sa[0][1] += q0 * k4.y; sa[0][2] += q0 * k4.z; sa[0][3] += q0 * k4.w;
                sa[1][0] += q1 * k4.x; sa[1][1] += q1 * k4.y; sa[1][2] += q1 * k4.z; sa[1][3] += q1 * k4.w;
                sa[2][0] += q2 * k4.x; sa[2][1] += q2 * k4.y; sa[2][2] += q2 * k4.z; sa[2][3] += q2 * k4.w;
                sa[3][0] += q3 * k4.x; sa[3][1] += q3 * k4.y; sa[3][2] += q3 * k4.z; sa[3][3] += q3 * k4.w;
            }
            __syncthreads();
        }

        // Write masked, scaled scores to smem
        #pragma unroll
        for (int ii = 0; ii < 4; ii++) {
            int r = ty * 4 + ii;
            #pragma unroll
            for (int jj = 0; jj < 4; jj++) {
                int s = tx * 4 + jj;
                float v = sa[ii][jj] * SCALE_F;
                if (sbase + s > qbase + r) v = -3.0e38f;
                S[r * 65 + s] = v;
            }
        }

        // Load V tile (64 x 128) while S settles
        #pragma unroll
        for (int i = tid; i < 64 * 128; i += 256) {
            int s = i >> 7, n = i & 127;
            v_s[s * 132 + n] = Vg[(size_t)(sbase + s) * VD + n];
        }
        __syncthreads();

        // --- Phase B: online softmax (4 lanes per row) ---
        {
            const int r  = tid >> 2;
            const int cg = tid & 3;
            float mo = m_s[r];
            float mx = mo;
            float vals[16];
            #pragma unroll
            for (int j = 0; j < 16; j++) {
                vals[j] = S[r * 65 + cg * 16 + j];
                mx = fmaxf(mx, vals[j]);
            }
            mx = fmaxf(mx, __shfl_xor_sync(0xffffffffu, mx, 1));
            mx = fmaxf(mx, __shfl_xor_sync(0xffffffffu, mx, 2));
            float scl  = __expf(mo - mx);
            float lsum = 0.0f;
            #pragma unroll
            for (int j = 0; j < 16; j++) {
                float p = __expf(vals[j] - mx);
                S[r * 65 + cg * 16 + j] = p;
                lsum += p;
            }
            lsum += __shfl_xor_sync(0xffffffffu, lsum, 1);
            lsum += __shfl_xor_sync(0xffffffffu, lsum, 2);
            if (cg == 0) {
                m_s[r]  = mx;
                l_s[r]  = l_s[r] * scl + lsum;
                sc_s[r] = scl;
            }
        }
        __syncthreads();

        // --- Phase C: rescale accumulators, then O += P V ---
        {
            float s0 = sc_s[ty * 4 + 0];
            float s1 = sc_s[ty * 4 + 1];
            float s2 = sc_s[ty * 4 + 2];
            float s3 = sc_s[ty * 4 + 3];
            #pragma unroll
            for (int jj = 0; jj < 8; jj++) {
                o[0][jj] *= s0; o[1][jj] *= s1; o[2][jj] *= s2; o[3][jj] *= s3;
            }
        }
        {
            const float* vp = v_s + tx * 8;
            const float* sp = S + (ty * 4) * 65;
            #pragma unroll 4
            for (int j = 0; j < 64; j++) {
                float4 v0 = *(const float4*)(vp + j * 132);
                float4 v1 = *(const float4*)(vp + j * 132 + 4);
                float p0 = sp[j];
                float p1 = sp[65 + j];
                float p2 = sp[130 + j];
                float p3 = sp[195 + j];
                o[0][0] += p0 * v0.x; o[0][1] += p0 * v0.y; o[0][2] += p0 * v0.z; o[0][3] += p0 * v0.w;
                o[0][4] += p0 * v1.x; o[0][5] += p0 * v1.y; o[0][6] += p0 * v1.z; o[0][7] += p0 * v1.w;
                o[1][0] += p1 * v0.x; o[1][1] += p1 * v0.y; o[1][2] += p1 * v0.z; o[1][3] += p1 * v0.w;
                o[1][4] += p1 * v1.x; o[1][5] += p1 * v1.y; o[1][6] += p1 * v1.z; o[1][7] += p1 * v1.w;
                o[2][0] += p2 * v0.x; o[2][1] += p2 * v0.y; o[2][2] += p2 * v0.z; o[2][3] += p2 * v0.w;
                o[2][4] += p2 * v1.x; o[2][5] += p2 * v1.y; o[2][6] += p2 * v1.z; o[2][7] += p2 * v1.w;
                o[3][0] += p3 * v0.x; o[3][1] += p3 * v0.y; o[3][2] += p3 * v0.z; o[3][3] += p3 * v0.w;
                o[3][4] += p3 * v1.x; o[3][5] += p3 * v1.y; o[3][6] += p3 * v1.z; o[3][7] += p3 * v1.w;
            }
        }
        __syncthreads();
    }

    // Epilogue: normalize and write (T, H*VD)
    #pragma unroll
    for (int ii = 0; ii < 4; ii++) {
        int t = qbase + ty * 4 + ii;
        float inv = 1.0f / l_s[ty * 4 + ii];
        float* dst = &out[(size_t)t * (HH * VD) + h * VD + tx * 8];
        #pragma unroll
        for (int jj = 0; jj < 8; jj++) dst[jj] = o[ii][jj] * inv;
    }
}

// ---------------------------------------------------------------------------
// Launch
// ---------------------------------------------------------------------------
extern "C" void kernel_launch(void* const* d_in, const int* in_sizes, int n_in,
                              void* d_out, int out_size)
{
    const float* query = (const float*)d_in[0];   // (T, H, 192)
    const float* kc    = (const float*)d_in[1];   // (T, 512)
    const float* kpe   = (const float*)d_in[2];   // (T, 64)
    const float* wkv   = (const float*)d_in[3];   // (512, 4096)
    const float* wuv   = (const float*)d_in[4];   // (16, 512, 128)
    float* out         = (float*)d_out;           // (T, 2048)

    // Projections: K (nope+rope) and effective V
    {
        dim3 grid(TT / 64, HH, 2);
        proj_kernel<<<grid, 256>>>(kc, wkv, wuv, kpe);
    }

    // Flash attention
    {
        const int smem_bytes = ATTN_SMEM_FLOATS * (int)sizeof(float);
        cudaFuncSetAttribute(attn_kernel, cudaFuncAttributeMaxDynamicSharedMemorySize,
                             smem_bytes);
        dim3 grid(TT / 64, HH);
        attn_kernel<<<grid, 256, smem_bytes>>>(query, out);
    }
}

// round 8
// speedup vs baseline: 1.1277x; 1.1277x over previous
#include <cuda_runtime.h>
#include <cuda_bf16.h>
#include <math.h>

#define TT   2048
#define HH   16
#define DQK  192
#define NOPE 128
#define ROPE 64
#define LORA 512
#define VD   128
#define SCALE_F (0.07216878364870322f)  // 1/sqrt(192)

// Scratch (allowed: __device__ globals, no runtime allocation)
__device__ float g_K[HH * TT * DQK];   // per-head K = [k_nope | k_pe]
__device__ float g_V[HH * TT * VD];    // per-head effective V = k_c @ w_uv[h]

// ---------------------------------------------------------------------------
// Projection kernel (unchanged from R7 — FMA-issue-bound already):
//   z==0: g_K[h][t][0:128] = k_c[t] @ w_kv_b[:, h*256 : h*256+128]
//         g_K[h][t][128:192] = k_pe[t]
//   z==1: g_V[h][t][:] = k_c[t] @ w_uv[h]
// ---------------------------------------------------------------------------
__global__ __launch_bounds__(256)
void proj_kernel(const float* __restrict__ kc, const float* __restrict__ wkv,
                 const float* __restrict__ wuv, const float* __restrict__ kpe)
{
    const int rbase = blockIdx.x * 64;
    const int h     = blockIdx.y;
    const int which = blockIdx.z;

    __shared__ float a_s[32 * 68];    // A chunk, transposed: a_s[l][row]
    __shared__ float b_s[32 * 132];   // B chunk: b_s[l][n]

    const int tid = threadIdx.x;
    const int ty  = tid >> 4;
    const int tx  = tid & 15;

    float acc[4][8];
    #pragma unroll
    for (int i = 0; i < 4; i++)
        #pragma unroll
        for (int j = 0; j < 8; j++) acc[i][j] = 0.0f;

    const float* Bp      = (which == 0) ? (wkv + h * 256) : (wuv + (size_t)h * LORA * VD);
    const int    bstride = (which == 0) ? (HH * 256) : VD;

    for (int lc = 0; lc < LORA; lc += 32) {
        #pragma unroll
        for (int i = tid; i < 64 * 32; i += 256) {
            int row = i >> 5, l = i & 31;
            a_s[l * 68 + row] = kc[(rbase + row) * LORA + lc + l];
        }
        #pragma unroll
        for (int i = tid; i < 32 * 128; i += 256) {
            int l = i >> 7, n = i & 127;
            b_s[l * 132 + n] = Bp[(size_t)(lc + l) * bstride + n];
        }
        __syncthreads();

        #pragma unroll
        for (int kk = 0; kk < 32; kk++) {
            float4 a4 = *(const float4*)&a_s[kk * 68 + ty * 4];
            float4 b0 = *(const float4*)&b_s[kk * 132 + tx * 8];
            float4 b1 = *(const float4*)&b_s[kk * 132 + tx * 8 + 4];
            float av[4] = {a4.x, a4.y, a4.z, a4.w};
            float bv[8] = {b0.x, b0.y, b0.z, b0.w, b1.x, b1.y, b1.z, b1.w};
            #pragma unroll
            for (int ii = 0; ii < 4; ii++)
                #pragma unroll
                for (int jj = 0; jj < 8; jj++)
                    acc[ii][jj] += av[ii] * bv[jj];
        }
        __syncthreads();
    }

    if (which == 0) {
        #pragma unroll
        for (int ii = 0; ii < 4; ii++) {
            int t = rbase + ty * 4 + ii;
            float* dst = &g_K[((size_t)h * TT + t) * DQK + tx * 8];
            #pragma unroll
            for (int jj = 0; jj < 8; jj++) dst[jj] = acc[ii][jj];
        }
        #pragma unroll
        for (int i = tid; i < 64 * 64; i += 256) {
            int row = i >> 6, dd = i & 63;
            g_K[((size_t)h * TT + rbase + row) * DQK + NOPE + dd] =
                kpe[(rbase + row) * ROPE + dd];
        }
    } else {
        #pragma unroll
        for (int ii = 0; ii < 4; ii++) {
            int t = rbase + ty * 4 + ii;
            float* dst = &g_V[((size_t)h * TT + t) * VD + tx * 8];
            #pragma unroll
            for (int jj = 0; jj < 8; jj++) dst[jj] = acc[ii][jj];
        }
    }
}

// ---------------------------------------------------------------------------
// Causal flash attention v2: 128-query x 64-key tiles, 256 threads.
// Per-thread: Phase A 8x4 scores (strided key cols), Phase C 8x8 output.
// smem: Q[128][192] | K[64][68] row-major | V[64][132] | S[128][68] | m/l/sc[128]
//     = 185,856 B dynamic. 1 CTA/SM. Grid (16 qtiles reversed, 16 heads).
// ---------------------------------------------------------------------------
#define ATTN_SMEM_FLOATS (128*192 + 64*68 + 64*132 + 128*68 + 3*128)

__global__ __launch_bounds__(256, 1)
void attn_kernel(const float* __restrict__ q, float* __restrict__ out)
{
    extern __shared__ float sm[];
    float* q_s  = sm;                        // 128*192 = 24576
    float* k_s  = q_s + 128 * 192;           // 64*68   =  4352  (k_s[s][d])
    float* v_s  = k_s + 64 * 68;             // 64*132  =  8448
    float* S    = v_s + 64 * 132;            // 128*68  =  8704
    float* m_s  = S + 128 * 68;              // 128
    float* l_s  = m_s + 128;                 // 128
    float* sc_s = l_s + 128;                 // 128

    const int h     = blockIdx.y;
    const int qt    = (int)gridDim.x - 1 - (int)blockIdx.x;  // big tiles first
    const int qbase = qt * 128;
    const int tid   = threadIdx.x;
    const int ty    = tid >> 4;              // 0..15 -> rows ty*8..+7
    const int tx    = tid & 15;              // 0..15 -> key cols {tx,tx+16,tx+32,tx+48}

    // Load Q tile (128 x 192), float4
    for (int i = tid; i < 128 * 48; i += 256) {
        int r = i / 48, dg = i - r * 48;
        *(float4*)&q_s[r * 192 + dg * 4] =
            *(const float4*)&q[((size_t)(qbase + r) * HH + h) * DQK + dg * 4];
    }
    if (tid < 128) { m_s[tid] = -3.0e38f; l_s[tid] = 0.0f; }

    float o[8][8];
    #pragma unroll
    for (int i = 0; i < 8; i++)
        #pragma unroll
        for (int j = 0; j < 8; j++) o[i][j] = 0.0f;

    __syncthreads();

    const float* Kg = g_K + (size_t)h * TT * DQK;
    const float* Vg = g_V + (size_t)h * TT * VD;
    const int ntiles = 2 * qt + 2;

    for (int tile = 0; tile < ntiles; tile++) {
        const int sbase = tile * 64;

        // --- Phase A: S = Q K^T over 3 chunks of 64 dims ---
        float sa[8][4];
        #pragma unroll
        for (int i = 0; i < 8; i++)
            #pragma unroll
            for (int j = 0; j < 4; j++) sa[i][j] = 0.0f;

        for (int c = 0; c < 3; c++) {
            // K chunk row-major [s][d], float4 staging (coalesced LDG, min-phase STS)
            #pragma unroll
            for (int it = 0; it < 4; it++) {
                int i = tid + it * 256;
                int s = i >> 4, dg = i & 15;
                *(float4*)&k_s[s * 68 + dg * 4] =
                    *(const float4*)&Kg[(size_t)(sbase + s) * DQK + c * 64 + dg * 4];
            }
            __syncthreads();

            const float* qp = q_s + (ty * 8) * 192 + c * 64;
            #pragma unroll 1
            for (int d0 = 0; d0 < 64; d0 += 4) {
                float4 k0 = *(const float4*)&k_s[(tx     ) * 68 + d0];
                float4 k1 = *(const float4*)&k_s[(tx + 16) * 68 + d0];
                float4 k2 = *(const float4*)&k_s[(tx + 32) * 68 + d0];
                float4 k3 = *(const float4*)&k_s[(tx + 48) * 68 + d0];
                #pragma unroll
                for (int ii = 0; ii < 8; ii++) {
                    float4 qv = *(const float4*)&qp[ii * 192 + d0];
                    sa[ii][0] += qv.x*k0.x; sa[ii][0] += qv.y*k0.y;
                    sa[ii][0] += qv.z*k0.z; sa[ii][0] += qv.w*k0.w;
                    sa[ii][1] += qv.x*k1.x; sa[ii][1] += qv.y*k1.y;
                    sa[ii][1] += qv.z*k1.z; sa[ii][1] += qv.w*k1.w;
                    sa[ii][2] += qv.x*k2.x; sa[ii][2] += qv.y*k2.y;
                    sa[ii][2] += qv.z*k2.z; sa[ii][2] += qv.w*k2.w;
                    sa[ii][3] += qv.x*k3.x; sa[ii][3] += qv.y*k3.y;
                    sa[ii][3] += qv.z*k3.z; sa[ii][3] += qv.w*k3.w;
                }
            }
            __syncthreads();
        }

        // Write scaled (+masked on diagonal tiles) scores. Col of sa[.][m] = tx+16m.
        if (tile >= 2 * qt) {
            #pragma unroll
            for (int ii = 0; ii < 8; ii++) {
                int r = ty * 8 + ii;
                #pragma unroll
                for (int m = 0; m < 4; m++) {
                    int scol = tx + 16 * m;
                    float v = sa[ii][m] * SCALE_F;
                    if (sbase + scol > qbase + r) v = -3.0e38f;
                    S[r * 68 + scol] = v;
                }
            }
        } else {
            #pragma unroll
            for (int ii = 0; ii < 8; ii++) {
                int r = ty * 8 + ii;
                #pragma unroll
                for (int m = 0; m < 4; m++)
                    S[r * 68 + tx + 16 * m] = sa[ii][m] * SCALE_F;
            }
        }

        // Load V tile (64 x 128), float4
        #pragma unroll
        for (int it = 0; it < 8; it++) {
            int i = tid + it * 256;
            int s = i >> 5, ng = i & 31;
            *(float4*)&v_s[s * 132 + ng * 4] =
                *(const float4*)&Vg[(size_t)(sbase + s) * VD + ng * 4];
        }
        __syncthreads();

        // --- Phase B: online softmax (2 lanes per row, 32 cols each) ---
        {
            const int r  = tid >> 1;
            const int cg = tid & 1;
            const float* srow = S + r * 68 + cg * 32;
            float mo = m_s[r];
            float mx = mo;
            #pragma unroll
            for (int j = 0; j < 32; j++) mx = fmaxf(mx, srow[j]);
            mx = fmaxf(mx, __shfl_xor_sync(0xffffffffu, mx, 1));
            float scl  = __expf(mo - mx);
            float lsum = 0.0f;
            float* srw = S + r * 68 + cg * 32;
            #pragma unroll
            for (int j = 0; j < 32; j++) {
                float p = __expf(srow[j] - mx);
                srw[j] = p;
                lsum += p;
            }
            lsum += __shfl_xor_sync(0xffffffffu, lsum, 1);
            if (cg == 0) {
                m_s[r]  = mx;
                l_s[r]  = l_s[r] * scl + lsum;
                sc_s[r] = scl;
            }
        }
        __syncthreads();

        // --- Phase C: rescale accumulators, then O += P V (8x8 per thread) ---
        {
            #pragma unroll
            for (int ii = 0; ii < 8; ii++) {
                float s = sc_s[ty * 8 + ii];
                #pragma unroll
                for (int jj = 0; jj < 8; jj++) o[ii][jj] *= s;
            }
        }
        {
            const float* vp = v_s + tx * 8;
            const float* sp = S + (ty * 8) * 68;
            #pragma unroll 1
            for (int j0 = 0; j0 < 64; j0 += 4) {
                float4 va[4][2];
                #pragma unroll
                for (int m = 0; m < 4; m++) {
                    va[m][0] = *(const float4*)&vp[(j0 + m) * 132];
                    va[m][1] = *(const float4*)&vp[(j0 + m) * 132 + 4];
                }
                #pragma unroll
                for (int ii = 0; ii < 8; ii++) {
                    float4 pv = *(const float4*)&sp[ii * 68 + j0];
                    float pm[4] = {pv.x, pv.y, pv.z, pv.w};
                    #pragma unroll
                    for (int m = 0; m < 4; m++) {
                        o[ii][0] += pm[m] * va[m][0].x;
                        o[ii][1] += pm[m] * va[m][0].y;
                        o[ii][2] += pm[m] * va[m][0].z;
                        o[ii][3] += pm[m] * va[m][0].w;
                        o[ii][4] += pm[m] * va[m][1].x;
                        o[ii][5] += pm[m] * va[m][1].y;
                        o[ii][6] += pm[m] * va[m][1].z;
                        o[ii][7] += pm[m] * va[m][1].w;
                    }
                }
            }
        }
        // No trailing sync needed: next tile's first smem write (k_s) is
        // followed by a __syncthreads before any thread reads it, and S/v_s
        // are only overwritten after further syncs.
    }

    // Epilogue: normalize and write (T, H*VD), float4
    #pragma unroll
    for (int ii = 0; ii < 8; ii++) {
        int t = qbase + ty * 8 + ii;
        float inv = 1.0f / l_s[ty * 8 + ii];
        float* dst = &out[(size_t)t * (HH * VD) + h * VD + tx * 8];
        float4 r0 = make_float4(o[ii][0]*inv, o[ii][1]*inv, o[ii][2]*inv, o[ii][3]*inv);
        float4 r1 = make_float4(o[ii][4]*inv, o[ii][5]*inv, o[ii][6]*inv, o[ii][7]*inv);
        *(float4*)dst       = r0;
        *(float4*)(dst + 4) = r1;
    }
}

// ---------------------------------------------------------------------------
// Launch
// ---------------------------------------------------------------------------
extern "C" void kernel_launch(void* const* d_in, const int* in_sizes, int n_in,
                              void* d_out, int out_size)
{
    const float* query = (const float*)d_in[0];   // (T, H, 192)
    const float* kc    = (const float*)d_in[1];   // (T, 512)
    const float* kpe   = (const float*)d_in[2];   // (T, 64)
    const float* wkv   = (const float*)d_in[3];   // (512, 4096)
    const float* wuv   = (const float*)d_in[4];   // (16, 512, 128)
    float* out         = (float*)d_out;           // (T, 2048)

    // Projections: K (nope+rope) and effective V
    {
        dim3 grid(TT / 64, HH, 2);
        proj_kernel<<<grid, 256>>>(kc, wkv, wuv, kpe);
    }

    // Flash attention
    {
        const int smem_bytes = ATTN_SMEM_FLOATS * (int)sizeof(float);
        cudaFuncSetAttribute(attn_kernel, cudaFuncAttributeMaxDynamicSharedMemorySize,
                             smem_bytes);
        dim3 grid(TT / 128, HH);
        attn_kernel<<<grid, 256, smem_bytes>>>(query, out);
    }
}